// round 4
// baseline (speedup 1.0000x reference)
#include <cuda_runtime.h>

#define NNODES 100000
#define EDGES  600000
#define INDIM  128
#define OUTDIM 256

// Scratch (static __device__ arrays: the sanctioned no-alloc workaround).
// All fully re-initialized every kernel_launch -> deterministic under graph replay.
__device__ float g_agg[(size_t)NNODES * INDIM];    // (1+eps)*x + scatter-add
__device__ float g_h1[(size_t)NNODES * OUTDIM];    // relu(h @ W1 + b1)
__device__ float g_W2s[OUTDIM * OUTDIM];           // W2 with BN scale folded into columns
__device__ float g_cbias[OUTDIM];                  // folded bias: (b2-mean)*scale + beta + bp
__device__ int   g_idx64;                          // 1 if edge_index is int64 on device

// ---------------- packed f32x2 helpers (FFMA2 path, PTX-only on sm_103a) ---------

__device__ __forceinline__ unsigned long long pack2(float lo, float hi) {
    unsigned long long r;
    asm("mov.b64 %0, {%1, %2};" : "=l"(r) : "f"(lo), "f"(hi));
    return r;
}
__device__ __forceinline__ void ffma2(unsigned long long& d, unsigned long long a,
                                      unsigned long long b) {
    asm("fma.rn.f32x2 %0, %1, %2, %0;" : "+l"(d) : "l"(a), "l"(b));
}
__device__ __forceinline__ float2 unpack2(unsigned long long v) {
    float2 f;
    asm("mov.b64 {%0, %1}, %2;" : "=f"(f.x), "=f"(f.y) : "l"(v));
    return f;
}

// ---------------- 0) probe: is edge_index int32 or int64? -----------------------
// int64 indices < 2^31 have zero high words at every odd 4-byte position.
// 64 random int32 indices in [0,100000) being all zero is impossible in practice.

__global__ void probe_idx_kernel(const int* __restrict__ ei32) {
    int all_zero = 1;
    for (int i = 1; i < 128; i += 2)
        if (ei32[i] != 0) { all_zero = 0; break; }
    g_idx64 = all_zero;
}

// ---------------- 1) init: g_agg = (1+eps) * x ----------------------------------

__global__ void init_agg_kernel(const float4* __restrict__ x4,
                                const float* __restrict__ epsp) {
    int i = blockIdx.x * blockDim.x + threadIdx.x;   // over NNODES*32 float4s
    float s = 1.0f + epsp[0];
    float4 v = x4[i];
    v.x *= s; v.y *= s; v.z *= s; v.w *= s;
    reinterpret_cast<float4*>(g_agg)[i] = v;
}

// ---------------- 2) scatter: g_agg[dst] += x[src] (one warp per edge) ----------

__global__ void scatter_kernel(const float4* __restrict__ x4,
                               const void* __restrict__ ei) {
    long long t = (long long)blockIdx.x * blockDim.x + threadIdx.x;
    int e    = (int)(t >> 5);
    int lane = (int)(t & 31);
    if (e >= EDGES) return;
    int s, d;
    if (g_idx64) {
        const long long* e64 = (const long long*)ei;
        s = (int)e64[e];
        d = (int)e64[EDGES + e];
    } else {
        const int* e32 = (const int*)ei;
        s = e32[e];
        d = e32[EDGES + e];
    }
    float4 v = x4[(size_t)s * (INDIM / 4) + lane];
    float* base = g_agg + (size_t)d * INDIM + lane * 4;
    atomicAdd(base + 0, v.x);   // return value unused -> ptxas emits RED
    atomicAdd(base + 1, v.y);
    atomicAdd(base + 2, v.z);
    atomicAdd(base + 3, v.w);
}

// ---------------- 3) fold BN into W2 + combined bias ----------------------------

__global__ void prescale_kernel(const float* __restrict__ W2,
                                const float* __restrict__ b2,
                                const float* __restrict__ gamma,
                                const float* __restrict__ beta,
                                const float* __restrict__ rmean,
                                const float* __restrict__ rvar,
                                const float* __restrict__ bp) {
    int c = threadIdx.x;         // 0..255 (output column)
    int r = blockIdx.x;          // 0..255 (W2 row)
    float sc = gamma[c] * rsqrtf(rvar[c] + 1e-5f);
    g_W2s[r * OUTDIM + c] = W2[r * OUTDIM + c] * sc;
    if (r == 0)
        g_cbias[c] = (b2[c] - rmean[c]) * sc + beta[c] + bp[c];
}

// ---------------- shared SGEMM mainloop (128x128 block tile, BK=8, 8x8/thread) --
// Warp tiling: 8 warps as 4(row) x 2(col); warp tile = 32 rows x 64 cols;
// lane as 4(row) x 8(col). A-side LDS.128 is conflict-free (4 distinct 32B
// segments per warp); B-side is at the 2-wavefront minimum (256B unique/warp).

__device__ __forceinline__ void gemm_accum(
    const float* __restrict__ A, int lda, int K, int rowStart,
    const float* __restrict__ B, int colStart,
    float (*As)[128], float (*Bs)[128],
    unsigned long long (&acc2)[8][4],
    int tRowIdx, int tColIdx, int tid) {

    const int innerRowA = tid >> 1;          // 0..127
    const int innerColA = (tid & 1) * 4;     // 0 or 4
    const int innerRowB = tid >> 5;          // 0..7
    const int innerColB = (tid & 31) * 4;    // 0..124

    for (int k0 = 0; k0 < K; k0 += 8) {
        // A tile [128 rows x 8 k], stored transposed As[k][row]
        int grow = rowStart + innerRowA;
        float4 a4 = make_float4(0.f, 0.f, 0.f, 0.f);
        if (grow < NNODES)
            a4 = *reinterpret_cast<const float4*>(
                A + (size_t)grow * lda + (k0 + innerColA));
        As[innerColA + 0][innerRowA] = a4.x;
        As[innerColA + 1][innerRowA] = a4.y;
        As[innerColA + 2][innerRowA] = a4.z;
        As[innerColA + 3][innerRowA] = a4.w;

        // B tile [8 k x 128 cols] (B row stride is always OUTDIM=256)
        float4 b4 = *reinterpret_cast<const float4*>(
            B + (size_t)(k0 + innerRowB) * OUTDIM + (colStart + innerColB));
        *reinterpret_cast<float4*>(&Bs[innerRowB][innerColB]) = b4;
        __syncthreads();

#pragma unroll
        for (int k = 0; k < 8; k++) {
            float4 m0 = *reinterpret_cast<const float4*>(&As[k][tRowIdx]);
            float4 m1 = *reinterpret_cast<const float4*>(&As[k][tRowIdx + 4]);
            unsigned long long n2[4];
#pragma unroll
            for (int j = 0; j < 4; j++)
                n2[j] = *reinterpret_cast<const unsigned long long*>(
                    &Bs[k][tColIdx + 2 * j]);
            float m[8] = {m0.x, m0.y, m0.z, m0.w, m1.x, m1.y, m1.z, m1.w};
#pragma unroll
            for (int i = 0; i < 8; i++) {
                unsigned long long a2 = pack2(m[i], m[i]);
#pragma unroll
                for (int j = 0; j < 4; j++)
                    ffma2(acc2[i][j], a2, n2[j]);
            }
        }
        __syncthreads();
    }
}

__device__ __forceinline__ void thread_tile_idx(int tid, int& tRowIdx, int& tColIdx) {
    int warpId = tid >> 5, lane = tid & 31;
    tRowIdx = (warpId >> 1) * 32 + (lane >> 3) * 8;   // warpRow(0..3)*32 + wr(0..3)*8
    tColIdx = (warpId & 1) * 64 + (lane & 7) * 8;     // warpCol(0..1)*64 + wc(0..7)*8
}

// ---------------- 4) GEMM1: g_h1 = relu(g_agg @ W1 + b1) ------------------------

__global__ __launch_bounds__(256) void gemm1_kernel(const float* __restrict__ W1,
                                                    const float* __restrict__ b1) {
    __shared__ float As[8][128];
    __shared__ float Bs[8][128];
    int tid = threadIdx.x;
    int tRowIdx, tColIdx;
    thread_tile_idx(tid, tRowIdx, tColIdx);
    int rowStart = blockIdx.x * 128;
    int colStart = blockIdx.y * 128;

    unsigned long long acc2[8][4];
#pragma unroll
    for (int i = 0; i < 8; i++)
#pragma unroll
        for (int j = 0; j < 4; j++) acc2[i][j] = 0ULL;

    gemm_accum(g_agg, INDIM, INDIM, rowStart, W1, colStart,
               As, Bs, acc2, tRowIdx, tColIdx, tid);

    float bb[8];
#pragma unroll
    for (int j = 0; j < 8; j++) bb[j] = b1[colStart + tColIdx + j];

#pragma unroll
    for (int i = 0; i < 8; i++) {
        int row = rowStart + tRowIdx + i;
        if (row < NNODES) {
            float* o = g_h1 + (size_t)row * OUTDIM + colStart + tColIdx;
            float4 v0, v1;
            float2 p;
            p = unpack2(acc2[i][0]); v0.x = fmaxf(p.x + bb[0], 0.f); v0.y = fmaxf(p.y + bb[1], 0.f);
            p = unpack2(acc2[i][1]); v0.z = fmaxf(p.x + bb[2], 0.f); v0.w = fmaxf(p.y + bb[3], 0.f);
            p = unpack2(acc2[i][2]); v1.x = fmaxf(p.x + bb[4], 0.f); v1.y = fmaxf(p.y + bb[5], 0.f);
            p = unpack2(acc2[i][3]); v1.z = fmaxf(p.x + bb[6], 0.f); v1.w = fmaxf(p.y + bb[7], 0.f);
            *reinterpret_cast<float4*>(o)     = v0;
            *reinterpret_cast<float4*>(o + 4) = v1;
        }
    }
}

// ---------------- 5) GEMM2: out = g_h1 @ W2s + x @ Wp + cbias -------------------

__global__ __launch_bounds__(256) void gemm2_kernel(const float* __restrict__ x,
                                                    const float* __restrict__ Wp,
                                                    float* __restrict__ out) {
    __shared__ float As[8][128];
    __shared__ float Bs[8][128];
    int tid = threadIdx.x;
    int tRowIdx, tColIdx;
    thread_tile_idx(tid, tRowIdx, tColIdx);
    int rowStart = blockIdx.x * 128;
    int colStart = blockIdx.y * 128;

    unsigned long long acc2[8][4];
#pragma unroll
    for (int i = 0; i < 8; i++)
#pragma unroll
        for (int j = 0; j < 4; j++) acc2[i][j] = 0ULL;

    // phase 1: h1 @ (BN-folded W2), K=256
    gemm_accum(g_h1, OUTDIM, OUTDIM, rowStart, g_W2s, colStart,
               As, Bs, acc2, tRowIdx, tColIdx, tid);
    // phase 2: x @ Wp, K=128 (same accumulators)
    gemm_accum(x, INDIM, INDIM, rowStart, Wp, colStart,
               As, Bs, acc2, tRowIdx, tColIdx, tid);

    float bb[8];
#pragma unroll
    for (int j = 0; j < 8; j++) bb[j] = g_cbias[colStart + tColIdx + j];

#pragma unroll
    for (int i = 0; i < 8; i++) {
        int row = rowStart + tRowIdx + i;
        if (row < NNODES) {
            float* o = out + (size_t)row * OUTDIM + colStart + tColIdx;
            float4 v0, v1;
            float2 p;
            p = unpack2(acc2[i][0]); v0.x = p.x + bb[0]; v0.y = p.y + bb[1];
            p = unpack2(acc2[i][1]); v0.z = p.x + bb[2]; v0.w = p.y + bb[3];
            p = unpack2(acc2[i][2]); v1.x = p.x + bb[4]; v1.y = p.y + bb[5];
            p = unpack2(acc2[i][3]); v1.z = p.x + bb[6]; v1.w = p.y + bb[7];
            *reinterpret_cast<float4*>(o)     = v0;
            *reinterpret_cast<float4*>(o + 4) = v1;
        }
    }
}

// ---------------- launch --------------------------------------------------------

extern "C" void kernel_launch(void* const* d_in, const int* in_sizes, int n_in,
                              void* d_out, int out_size) {
    const float* x     = (const float*)d_in[0];
    const void*  ei    = d_in[1];               // [2, E]; dtype probed on device
    const float* eps   = (const float*)d_in[2];
    const float* W1    = (const float*)d_in[3];
    const float* b1    = (const float*)d_in[4];
    const float* W2    = (const float*)d_in[5];
    const float* b2    = (const float*)d_in[6];
    const float* gamma = (const float*)d_in[7];
    const float* beta  = (const float*)d_in[8];
    const float* rmean = (const float*)d_in[9];
    const float* rvar  = (const float*)d_in[10];
    const float* Wp    = (const float*)d_in[11];
    const float* bp    = (const float*)d_in[12];
    float* out = (float*)d_out;

    (void)in_sizes; (void)n_in; (void)out_size;

    // 0) probe edge_index dtype (1 thread; pure function of input)
    probe_idx_kernel<<<1, 1>>>((const int*)ei);
    // 1) agg = (1+eps)*x           (NNODES*32 float4s = 3.2M threads, exact grid)
    init_agg_kernel<<<(NNODES * (INDIM / 4)) / 256, 256>>>((const float4*)x, eps);
    // 2) agg[dst] += x[src]        (one warp per edge)
    scatter_kernel<<<(EDGES * 32) / 256, 256>>>((const float4*)x, ei);
    // 3) fold BN into W2 / bias
    prescale_kernel<<<OUTDIM, OUTDIM>>>(W2, b2, gamma, beta, rmean, rvar, bp);
    // 4) h1 = relu(agg @ W1 + b1)
    dim3 grid((NNODES + 127) / 128, OUTDIM / 128);
    gemm1_kernel<<<grid, 256>>>(W1, b1);
    // 5) out = h1 @ W2s + x @ Wp + cbias
    gemm2_kernel<<<grid, 256>>>(x, Wp, out);
}

// round 6
// speedup vs baseline: 1.1997x; 1.1997x over previous
#include <cuda_runtime.h>

#define NNODES 100000
#define EDGES  600000
#define INDIM  128
#define OUTDIM 256

// Scratch (static __device__ arrays: the sanctioned no-alloc workaround).
__device__ float g_agg[(size_t)NNODES * INDIM];    // (1+eps)*x + scatter-add
__device__ float g_h1[(size_t)NNODES * OUTDIM];    // relu(h @ W1 + b1)
__device__ float g_W2s[OUTDIM * OUTDIM];           // W2 with BN scale folded into columns
__device__ float g_cbias[OUTDIM];                  // folded bias: (b2-mean)*scale + beta + bp
__device__ int   g_idx64;                          // 1 if edge_index is int64 on device

// ---------------- packed f32x2 helpers (FFMA2 path, PTX-only on sm_103a) ---------

__device__ __forceinline__ unsigned long long pack2(float lo, float hi) {
    unsigned long long r;
    asm("mov.b64 %0, {%1, %2};" : "=l"(r) : "f"(lo), "f"(hi));
    return r;
}
__device__ __forceinline__ void ffma2(unsigned long long& d, unsigned long long a,
                                      unsigned long long b) {
    asm("fma.rn.f32x2 %0, %1, %2, %0;" : "+l"(d) : "l"(a), "l"(b));
}
__device__ __forceinline__ float2 unpack2(unsigned long long v) {
    float2 f;
    asm("mov.b64 {%0, %1}, %2;" : "=f"(f.x), "=f"(f.y) : "l"(v));
    return f;
}

// ---------------- 1) init: g_agg = (1+eps)*x ; thread 0 probes idx dtype --------
// int64 indices < 2^31 have zero high words at every odd 4-byte position.
// 64 random int32 indices in [0,100000) being all zero is impossible in practice.

__global__ void init_agg_kernel(const float4* __restrict__ x4,
                                const float* __restrict__ epsp,
                                const int* __restrict__ ei32) {
    int i = blockIdx.x * blockDim.x + threadIdx.x;   // over NNODES*32 float4s
    if (i == 0) {
        int all_zero = 1;
        for (int k = 1; k < 128; k += 2)
            if (ei32[k] != 0) { all_zero = 0; break; }
        g_idx64 = all_zero;
    }
    float s = 1.0f + epsp[0];
    float4 v = x4[i];
    v.x *= s; v.y *= s; v.z *= s; v.w *= s;
    reinterpret_cast<float4*>(g_agg)[i] = v;
}

// ---------------- 2) scatter: g_agg[dst] += x[src] (one warp per edge) ----------
// One red.global.add.v4.f32 per lane: 4x fewer atomic ops at the LTS.

__global__ void scatter_kernel(const float4* __restrict__ x4,
                               const void* __restrict__ ei) {
    int t = blockIdx.x * blockDim.x + threadIdx.x;
    int e    = t >> 5;
    int lane = t & 31;
    int s, d;
    if (g_idx64) {
        const long long* e64 = (const long long*)ei;
        s = (int)e64[e];
        d = (int)e64[EDGES + e];
    } else {
        const int* e32 = (const int*)ei;
        s = e32[e];
        d = e32[EDGES + e];
    }
    float4 v = x4[(size_t)s * (INDIM / 4) + lane];
    float* base = g_agg + (size_t)d * INDIM + lane * 4;
    asm volatile("red.global.add.v4.f32 [%0], {%1, %2, %3, %4};"
                 :: "l"(base), "f"(v.x), "f"(v.y), "f"(v.z), "f"(v.w)
                 : "memory");
}

// ---------------- 3) fold BN into W2 + combined bias ----------------------------

__global__ void prescale_kernel(const float* __restrict__ W2,
                                const float* __restrict__ b2,
                                const float* __restrict__ gamma,
                                const float* __restrict__ beta,
                                const float* __restrict__ rmean,
                                const float* __restrict__ rvar,
                                const float* __restrict__ bp) {
    int c = threadIdx.x;         // 0..255 (output column)
    int r = blockIdx.x;          // 0..255 (W2 row)
    float sc = gamma[c] * rsqrtf(rvar[c] + 1e-5f);
    g_W2s[r * OUTDIM + c] = W2[r * OUTDIM + c] * sc;
    if (r == 0)
        g_cbias[c] = (b2[c] - rmean[c]) * sc + beta[c] + bp[c];
}

// ---------------- double-buffered SGEMM mainloop --------------------------------
// 128x128 block tile, BK=8, 8x8/thread, FFMA2 accumulators.
// Two smem buffers; global loads for tile i+1 issued before computing tile i;
// one __syncthreads per K-step. unroll 2 keeps the buffer index static without
// exploding code size past the I$ sweet spot.

template <int K>
__device__ __forceinline__ void gemm_accum(
    const float* __restrict__ A, int lda, int rowStart,
    const float* __restrict__ B, int colStart,
    float (&As)[2][8][128], float (&Bs)[2][8][128],
    unsigned long long (&acc2)[8][4],
    int tRowIdx, int tColIdx, int tid) {

    const int innerRowA = tid >> 1;          // 0..127
    const int innerColA = (tid & 1) * 4;     // 0 or 4
    const int innerRowB = tid >> 5;          // 0..7
    const int innerColB = (tid & 31) * 4;    // 0..124

    const int grow = rowStart + innerRowA;
    const bool aok = grow < NNODES;
    const float* aptr = A + (size_t)grow * lda + innerColA;
    const float* bptr = B + (size_t)innerRowB * OUTDIM + (colStart + innerColB);

    // Protect smem reuse across phases (gemm2 calls this twice).
    __syncthreads();
    float4 a4 = aok ? *reinterpret_cast<const float4*>(aptr)
                    : make_float4(0.f, 0.f, 0.f, 0.f);
    float4 b4 = *reinterpret_cast<const float4*>(bptr);
    As[0][innerColA + 0][innerRowA] = a4.x;
    As[0][innerColA + 1][innerRowA] = a4.y;
    As[0][innerColA + 2][innerRowA] = a4.z;
    As[0][innerColA + 3][innerRowA] = a4.w;
    *reinterpret_cast<float4*>(&Bs[0][innerRowB][innerColB]) = b4;
    __syncthreads();

    constexpr int NIT = K / 8;
#pragma unroll 2
    for (int it = 0; it < NIT; it++) {
        const int cur = it & 1;
        float4 na, nb;
        if (it + 1 < NIT) {
            na = aok ? *reinterpret_cast<const float4*>(aptr + (it + 1) * 8)
                     : make_float4(0.f, 0.f, 0.f, 0.f);
            nb = *reinterpret_cast<const float4*>(bptr + (size_t)(it + 1) * 8 * OUTDIM);
        }
#pragma unroll
        for (int k = 0; k < 8; k++) {
            float4 m0 = *reinterpret_cast<const float4*>(&As[cur][k][tRowIdx]);
            float4 m1 = *reinterpret_cast<const float4*>(&As[cur][k][tRowIdx + 4]);
            unsigned long long n2[4];
#pragma unroll
            for (int j = 0; j < 4; j++)
                n2[j] = *reinterpret_cast<const unsigned long long*>(
                    &Bs[cur][k][tColIdx + 2 * j]);
            float m[8] = {m0.x, m0.y, m0.z, m0.w, m1.x, m1.y, m1.z, m1.w};
#pragma unroll
            for (int i = 0; i < 8; i++) {
                unsigned long long a2 = pack2(m[i], m[i]);
#pragma unroll
                for (int j = 0; j < 4; j++)
                    ffma2(acc2[i][j], a2, n2[j]);
            }
        }
        if (it + 1 < NIT) {
            As[cur ^ 1][innerColA + 0][innerRowA] = na.x;
            As[cur ^ 1][innerColA + 1][innerRowA] = na.y;
            As[cur ^ 1][innerColA + 2][innerRowA] = na.z;
            As[cur ^ 1][innerColA + 3][innerRowA] = na.w;
            *reinterpret_cast<float4*>(&Bs[cur ^ 1][innerRowB][innerColB]) = nb;
            __syncthreads();
        }
    }
}

__device__ __forceinline__ void thread_tile_idx(int tid, int& tRowIdx, int& tColIdx) {
    int warpId = tid >> 5, lane = tid & 31;
    tRowIdx = (warpId >> 1) * 32 + (lane >> 3) * 8;   // warpRow(0..3)*32 + wr(0..3)*8
    tColIdx = (warpId & 1) * 64 + (lane & 7) * 8;     // warpCol(0..1)*64 + wc(0..7)*8
}

// ---------------- 4) GEMM1: g_h1 = relu(g_agg @ W1 + b1) ------------------------

__global__ __launch_bounds__(256, 2) void gemm1_kernel(const float* __restrict__ W1,
                                                       const float* __restrict__ b1) {
    __shared__ float As[2][8][128];
    __shared__ float Bs[2][8][128];
    int tid = threadIdx.x;
    int tRowIdx, tColIdx;
    thread_tile_idx(tid, tRowIdx, tColIdx);
    int rowStart = blockIdx.x * 128;
    int colStart = blockIdx.y * 128;

    unsigned long long acc2[8][4];
#pragma unroll
    for (int i = 0; i < 8; i++)
#pragma unroll
        for (int j = 0; j < 4; j++) acc2[i][j] = 0ULL;

    gemm_accum<INDIM>(g_agg, INDIM, rowStart, W1, colStart,
                      As, Bs, acc2, tRowIdx, tColIdx, tid);

    float bb[8];
#pragma unroll
    for (int j = 0; j < 8; j++) bb[j] = b1[colStart + tColIdx + j];

#pragma unroll
    for (int i = 0; i < 8; i++) {
        int row = rowStart + tRowIdx + i;
        if (row < NNODES) {
            float* o = g_h1 + (size_t)row * OUTDIM + colStart + tColIdx;
            float4 v0, v1;
            float2 p;
            p = unpack2(acc2[i][0]); v0.x = fmaxf(p.x + bb[0], 0.f); v0.y = fmaxf(p.y + bb[1], 0.f);
            p = unpack2(acc2[i][1]); v0.z = fmaxf(p.x + bb[2], 0.f); v0.w = fmaxf(p.y + bb[3], 0.f);
            p = unpack2(acc2[i][2]); v1.x = fmaxf(p.x + bb[4], 0.f); v1.y = fmaxf(p.y + bb[5], 0.f);
            p = unpack2(acc2[i][3]); v1.z = fmaxf(p.x + bb[6], 0.f); v1.w = fmaxf(p.y + bb[7], 0.f);
            *reinterpret_cast<float4*>(o)     = v0;
            *reinterpret_cast<float4*>(o + 4) = v1;
        }
    }
}

// ---------------- 5) GEMM2: out = g_h1 @ W2s + x @ Wp + cbias -------------------

__global__ __launch_bounds__(256, 2) void gemm2_kernel(const float* __restrict__ x,
                                                       const float* __restrict__ Wp,
                                                       float* __restrict__ out) {
    __shared__ float As[2][8][128];
    __shared__ float Bs[2][8][128];
    int tid = threadIdx.x;
    int tRowIdx, tColIdx;
    thread_tile_idx(tid, tRowIdx, tColIdx);
    int rowStart = blockIdx.x * 128;
    int colStart = blockIdx.y * 128;

    unsigned long long acc2[8][4];
#pragma unroll
    for (int i = 0; i < 8; i++)
#pragma unroll
        for (int j = 0; j < 4; j++) acc2[i][j] = 0ULL;

    // phase 1: h1 @ (BN-folded W2), K=256
    gemm_accum<OUTDIM>(g_h1, OUTDIM, rowStart, g_W2s, colStart,
                       As, Bs, acc2, tRowIdx, tColIdx, tid);
    // phase 2: x @ Wp, K=128 (same accumulators)
    gemm_accum<INDIM>(x, INDIM, rowStart, Wp, colStart,
                      As, Bs, acc2, tRowIdx, tColIdx, tid);

    float bb[8];
#pragma unroll
    for (int j = 0; j < 8; j++) bb[j] = g_cbias[colStart + tColIdx + j];

#pragma unroll
    for (int i = 0; i < 8; i++) {
        int row = rowStart + tRowIdx + i;
        if (row < NNODES) {
            float* o = out + (size_t)row * OUTDIM + colStart + tColIdx;
            float4 v0, v1;
            float2 p;
            p = unpack2(acc2[i][0]); v0.x = p.x + bb[0]; v0.y = p.y + bb[1];
            p = unpack2(acc2[i][1]); v0.z = p.x + bb[2]; v0.w = p.y + bb[3];
            p = unpack2(acc2[i][2]); v1.x = p.x + bb[4]; v1.y = p.y + bb[5];
            p = unpack2(acc2[i][3]); v1.z = p.x + bb[6]; v1.w = p.y + bb[7];
            *reinterpret_cast<float4*>(o)     = v0;
            *reinterpret_cast<float4*>(o + 4) = v1;
        }
    }
}

// ---------------- launch --------------------------------------------------------

extern "C" void kernel_launch(void* const* d_in, const int* in_sizes, int n_in,
                              void* d_out, int out_size) {
    const float* x     = (const float*)d_in[0];
    const void*  ei    = d_in[1];               // [2, E]; dtype probed on device
    const float* eps   = (const float*)d_in[2];
    const float* W1    = (const float*)d_in[3];
    const float* b1    = (const float*)d_in[4];
    const float* W2    = (const float*)d_in[5];
    const float* b2    = (const float*)d_in[6];
    const float* gamma = (const float*)d_in[7];
    const float* beta  = (const float*)d_in[8];
    const float* rmean = (const float*)d_in[9];
    const float* rvar  = (const float*)d_in[10];
    const float* Wp    = (const float*)d_in[11];
    const float* bp    = (const float*)d_in[12];
    float* out = (float*)d_out;

    (void)in_sizes; (void)n_in; (void)out_size;

    // 1) agg = (1+eps)*x + dtype probe   (exact grid: 3.2M float4s)
    init_agg_kernel<<<(NNODES * (INDIM / 4)) / 256, 256>>>((const float4*)x, eps,
                                                           (const int*)ei);
    // 2) agg[dst] += x[src]              (one warp per edge, v4 RED)
    scatter_kernel<<<(EDGES * 32) / 256, 256>>>((const float4*)x, ei);
    // 3) fold BN into W2 / bias
    prescale_kernel<<<OUTDIM, OUTDIM>>>(W2, b2, gamma, beta, rmean, rvar, bp);
    // 4) h1 = relu(agg @ W1 + b1)
    dim3 grid((NNODES + 127) / 128, OUTDIM / 128);
    gemm1_kernel<<<grid, 256>>>(W1, b1);
    // 5) out = h1 @ W2s + x @ Wp + cbias
    gemm2_kernel<<<grid, 256>>>(x, Wp, out);
}